// round 16
// baseline (speedup 1.0000x reference)
#include <cuda_runtime.h>
#include <cuda_bf16.h>
#include <stdint.h>

#define NB 256
#define ND 131072
#define KC 64                       /* fp32 cols per chunk */
#define TOTCHUNK (ND / KC)          /* 2048 */
#define NSD 42                      /* diag splits per diag quadrant */
#define NSO 63                      /* off-diag splits */
#define GRID_GRAM (2 * NSD + NSO)   /* 147 CTAs = 1 full wave */
#define NBNB (NB * NB)

/* ------------------------- device scratch (static, no allocs) ------------ */
__device__ float    g_partials[(size_t)NSO * NBNB];     /* 16.1 MB */
__device__ float    g_psum[NSD * NB];
__device__ float    g_psumsq[NSD * NB];
__device__ unsigned g_pmask[NSD * NB];
__device__ double   g_T[NB];
__device__ float    g_acc1[NB];
__device__ unsigned g_done;          /* zero-init; reset by last CTA */
__device__ float    g_p;
__device__ float    g_scale;

/* ------------------------- helpers --------------------------------------- */
__device__ __forceinline__ uint32_t smem_u32(const void* p) {
    uint32_t a;
    asm("{ .reg .u64 t; cvta.to.shared.u64 t, %1; cvt.u32.u64 %0, t; }"
        : "=r"(a) : "l"(p));
    return a;
}
__device__ __forceinline__ uint32_t swz(uint32_t off) {
    return off ^ ((off >> 3) & 0x70);   /* SW128: bits[6:4] ^= bits[9:7] */
}
__device__ __forceinline__ uint32_t pack_bf16x2(float lo, float hi) {
    uint32_t r;
    asm("cvt.rn.bf16x2.f32 %0, %1, %2;" : "=r"(r) : "f"(hi), "f"(lo));
    return r;
}
__device__ __forceinline__ uint32_t round_bit(float v) {
    int iv = __float2int_rn(v);            /* ties-to-even == jnp.round */
    unsigned b = (unsigned)(iv + 16);      /* N(0,1): |round(x)| <= ~6  */
    return (b < 32u) ? (1u << b) : 0u;
}

#define LDSM4(r0_, r1_, r2_, r3_, addr)                                        \
    asm volatile("ldmatrix.sync.aligned.m8n8.x4.shared.b16 {%0,%1,%2,%3}, [%4];"\
                 : "=r"(r0_), "=r"(r1_), "=r"(r2_), "=r"(r3_) : "r"(addr))

#define MMA16816(d, a, b)                                                      \
    asm volatile("mma.sync.aligned.m16n8k16.row.col.f32.bf16.bf16.f32 "        \
                 "{%0,%1,%2,%3},{%4,%5,%6,%7},{%8,%9},{%0,%1,%2,%3};"          \
                 : "+f"((d)[0]), "+f"((d)[1]), "+f"((d)[2]), "+f"((d)[3])      \
                 : "r"((a)[0]), "r"((a)[1]), "r"((a)[2]), "r"((a)[3]),         \
                   "r"((b)[0]), "r"((b)[1]))

/* ------------------------- kernel 1: fused stats + bf16 Gram -------------- */
/* grid = 147 CTAs = single wave; 1024 threads (32 warps) per CTA.
   R15 (16 warps): occ 25%, issue 34.5%, tensor 30.9% -> latency-bound;
   doubling warps again, warp tile 16x32 (accum 16 regs/thread).
     b in [0,42):   t=0 diag C[0:128,0:128]
     b in [42,84):  t=1 diag C[128:256,128:256]
     b in [84,147): t=2 offd C[0:128,128:256] (+ transpose quadrant)
   smem: double-buffered 128x64 bf16 tiles for A and B (SW128), 64 KB dynamic. */
__global__ __launch_bounds__(1024, 1) void k_gram(const float* __restrict__ X) {
    extern __shared__ unsigned char smem[];

    const int tid = threadIdx.x;
    const int wid = tid >> 5;
    const int L   = tid & 31;

    const int b = blockIdx.x;
    int t, s;
    if (b < NSD)            { t = 0; s = b; }
    else if (b < 2 * NSD)   { t = 1; s = b - NSD; }
    else                    { t = 2; s = b - 2 * NSD; }
    const int m0 = (t == 1) ? 128 : 0;
    const int n0 = (t == 0) ? 0 : 128;
    const bool offd = (t == 2);
    const int NSPL = offd ? NSO : NSD;

    const int kc0 = (s * TOTCHUNK) / NSPL;
    const int kc1 = ((s + 1) * TOTCHUNK) / NSPL;
    const int nch = kc1 - kc0;
    const size_t kbase = (size_t)kc0 * KC;

    /* loader mapping: 16 float4-columns x 64 row-groups, 2 rows/thread/tile */
    const int c4 = tid & 15;
    const int rr = tid >> 4;                /* 0..63; rows rr and rr+64 */
    const float* Ap = X + (size_t)(m0 + rr) * ND + kbase + c4 * 4;
    const float* Bp = X + (size_t)(n0 + rr) * ND + kbase + c4 * 4;
    const size_t rstride = (size_t)64 * ND;

    const uint32_t smem_base = smem_u32(smem);

    float    sacc[2], qacc[2];
    uint32_t macc[2];
#pragma unroll
    for (int i = 0; i < 2; i++) { sacc[i] = 0.f; qacc[i] = 0.f; macc[i] = 0u; }

    float4 va[2], vb[2];

    /* ---- prologue: chunk 0 -> buffer 0 ---- */
#pragma unroll
    for (int i = 0; i < 2; i++) va[i] = *(const float4*)(Ap + i * rstride);
    if (offd) {
#pragma unroll
        for (int i = 0; i < 2; i++) vb[i] = *(const float4*)(Bp + i * rstride);
    }
    {
        unsigned char* a_t = smem;                    /* buf0 A */
        unsigned char* b_t = smem + 16384;            /* buf0 B */
#pragma unroll
        for (int i = 0; i < 2; i++) {
            if (!offd) {
                float4 w = va[i];
                sacc[i] += (w.x + w.y) + (w.z + w.w);
                qacc[i] += w.x * w.x + w.y * w.y + w.z * w.z + w.w * w.w;
                macc[i] |= round_bit(w.x) | round_bit(w.y) |
                           round_bit(w.z) | round_bit(w.w);
            }
            uint32_t off = swz((uint32_t)((rr + 64 * i) * 128 + c4 * 8));
            uint2 w2;
            w2.x = pack_bf16x2(va[i].x, va[i].y);
            w2.y = pack_bf16x2(va[i].z, va[i].w);
            *(uint2*)(a_t + off) = w2;
            if (offd) {
                uint2 u2;
                u2.x = pack_bf16x2(vb[i].x, vb[i].y);
                u2.y = pack_bf16x2(vb[i].z, vb[i].w);
                *(uint2*)(b_t + off) = u2;
            }
        }
    }
    __syncthreads();

    /* ---- mainloop ---- */
    const int wm = wid & 7;          /* 8 m-blocks of 16 rows */
    const int wn = wid >> 3;         /* 4 n-blocks of 32 cols */
    float c[4][4];
#pragma unroll
    for (int nf = 0; nf < 4; nf++)
#pragma unroll
        for (int r = 0; r < 4; r++) c[nf][r] = 0.f;

    const uint32_t arow_l = (uint32_t)(wm * 16 + (L & 15));
    const uint32_t ak_l   = (uint32_t)(((L >> 4) & 1) * 16);
    const uint32_t bn_l   = (uint32_t)(wn * 32 + (L & 7) + ((L >> 4) & 1) * 8);
    const uint32_t bk_l   = (uint32_t)(((L >> 3) & 1) * 16);

    for (int h = 0; h < nch; ++h) {
        const int cur = h & 1, nxt = cur ^ 1;
        const bool more = (h + 1 < nch);

        if (more) {
            const float* pa = Ap + (size_t)(h + 1) * KC;
#pragma unroll
            for (int i = 0; i < 2; i++) va[i] = *(const float4*)(pa + i * rstride);
            if (offd) {
                const float* pb = Bp + (size_t)(h + 1) * KC;
#pragma unroll
                for (int i = 0; i < 2; i++) vb[i] = *(const float4*)(pb + i * rstride);
            }
        }

        /* compute on buffer cur */
        const uint32_t abase = smem_base + (uint32_t)cur * 32768u;
        const uint32_t bbase = offd ? (abase + 16384u) : abase;
#pragma unroll
        for (int ks = 0; ks < 4; ks++) {
            uint32_t a[4], bb[4][2];
            {
                uint32_t addr = abase +
                    swz(arow_l * 128 + (uint32_t)ks * 32 + ak_l);
                LDSM4(a[0], a[1], a[2], a[3], addr);
            }
#pragma unroll
            for (int ng = 0; ng < 2; ng++) {
                uint32_t addr = bbase +
                    swz((bn_l + ng * 16) * 128 + (uint32_t)ks * 32 + bk_l);
                LDSM4(bb[2 * ng][0], bb[2 * ng][1], bb[2 * ng + 1][0],
                      bb[2 * ng + 1][1], addr);
            }
#pragma unroll
            for (int nf = 0; nf < 4; nf++)
                MMA16816(c[nf], a, bb[nf]);
        }

        if (more) {
            unsigned char* a_t = smem + nxt * 32768;
            unsigned char* b_t = a_t + 16384;
#pragma unroll
            for (int i = 0; i < 2; i++) {
                if (!offd) {
                    float4 w = va[i];
                    sacc[i] += (w.x + w.y) + (w.z + w.w);
                    qacc[i] += w.x * w.x + w.y * w.y + w.z * w.z + w.w * w.w;
                    macc[i] |= round_bit(w.x) | round_bit(w.y) |
                               round_bit(w.z) | round_bit(w.w);
                }
                uint32_t off = swz((uint32_t)((rr + 64 * i) * 128 + c4 * 8));
                uint2 w2;
                w2.x = pack_bf16x2(va[i].x, va[i].y);
                w2.y = pack_bf16x2(va[i].z, va[i].w);
                *(uint2*)(a_t + off) = w2;
                if (offd) {
                    uint2 u2;
                    u2.x = pack_bf16x2(vb[i].x, vb[i].y);
                    u2.y = pack_bf16x2(vb[i].z, vb[i].w);
                    *(uint2*)(b_t + off) = u2;
                }
            }
        }
        __syncthreads();
    }

    /* ---- per-split row stats (deterministic: no fp32 atomics) ----
       the 16 threads sharing row-group rr are consecutive tids -> shfl w16 */
    if (!offd) {
#pragma unroll
        for (int i = 0; i < 2; i++) {
            float ss = sacc[i], qq = qacc[i];
            uint32_t mm = macc[i];
#pragma unroll
            for (int o = 8; o > 0; o >>= 1) {
                ss += __shfl_down_sync(0xffffffffu, ss, o, 16);
                qq += __shfl_down_sync(0xffffffffu, qq, o, 16);
                mm |= __shfl_down_sync(0xffffffffu, mm, o, 16);
            }
            if (c4 == 0) {
                int row = m0 + rr + 64 * i;
                g_psum[s * NB + row]   = ss;
                g_psumsq[s * NB + row] = qq;
                g_pmask[s * NB + row]  = mm;
            }
        }
    }

    /* ---- epilogue: accumulators -> per-split partial Gram ---- */
    {
        const int gid = L >> 2, tig = L & 3;
        float* P = g_partials + (size_t)s * NBNB;
#pragma unroll
        for (int nf = 0; nf < 4; nf++) {
            int row = m0 + wm * 16 + gid;
            int col = n0 + wn * 32 + nf * 8 + tig * 2;
            float2 lo = make_float2(c[nf][0], c[nf][1]);
            float2 hi = make_float2(c[nf][2], c[nf][3]);
            *(float2*)(P + (size_t)row * NB + col)       = lo;
            *(float2*)(P + (size_t)(row + 8) * NB + col) = hi;
            if (offd) {   /* transpose quadrant */
                P[(size_t)col * NB + row]           = c[nf][0];
                P[(size_t)(col + 1) * NB + row]     = c[nf][1];
                P[(size_t)col * NB + row + 8]       = c[nf][2];
                P[(size_t)(col + 1) * NB + row + 8] = c[nf][3];
            }
        }
    }
}

/* ------------------------- kernel 2: fused epilogue ----------------------- */
/* 256 CTAs, one per Gram row i:
     - reduce partial slabs directly (diag quadrant sums NSD slabs, off-diag
       NSO slabs; coalesced, L2-resident)
     - per-row |corr| sum and row total T_i
     - the LAST CTA to finish (atomic counter) computes p; counter reset so
       every graph replay behaves identically. */
__global__ __launch_bounds__(256) void k_epilogue() {
    __shared__ float    sh_s[NB], sh_inv[NB], sh_q[NB];
    __shared__ double   dred[NB];
    __shared__ float    fred[NB];
    __shared__ unsigned mred[NB];
    __shared__ bool     is_last;

    const int j = threadIdx.x;
    const int i = blockIdx.x;

    /* per-column stats (recomputed per CTA; L2-hot) */
    float s_j = 0.f, q_j = 0.f;
#pragma unroll
    for (int s = 0; s < NSD; s++) {
        s_j += g_psum[s * NB + j];
        q_j += g_psumsq[s * NB + j];
    }
    const float invD  = 1.0f / (float)ND;
    const float invD1 = 1.0f / (float)(ND - 1);
    sh_s[j]   = s_j;
    sh_q[j]   = q_j;
    sh_inv[j] = rsqrtf((q_j - s_j * s_j * invD) * invD1);
    __syncthreads();

    /* G_ij = sum over slabs of partials (quadrant-dependent count) */
    const int cnt = ((i < 128) == (j < 128)) ? NSD : NSO;
    const float* P = g_partials + (size_t)i * NB + j;
    float g = 0.f;
#pragma unroll 4
    for (int s = 0; s < cnt; s++) g += P[(size_t)s * NBNB];
    if (j == i) g = sh_q[i];                   /* exact diagonal */

    const float s_i = sh_s[i], inv_i = sh_inv[i];
    float cov  = (g - s_i * sh_s[j] * invD) * invD1;
    float corr = cov * inv_i * sh_inv[j];
    corr = fminf(1.0f, fmaxf(-1.0f, corr));

    dred[j] = (double)g;
    fred[j] = fabsf(corr);
    __syncthreads();
    for (int o = 128; o > 0; o >>= 1) {
        if (j < o) { dred[j] += dred[j + o]; fred[j] += fred[j + o]; }
        __syncthreads();
    }
    if (j == 0) {
        g_T[i]    = dred[0];
        g_acc1[i] = fred[0];
        __threadfence();
        unsigned v = atomicAdd(&g_done, 1u);
        is_last = (v == NB - 1);
    }
    __syncthreads();
    if (!is_last) return;
    __threadfence();

    /* ---- final scalar phase (one CTA); thread j plays role of row j ---- */
    const double T_j   = g_T[j];
    const float  f1    = g_acc1[j] * (1.0f / (float)NB);
    const float  qrow  = sh_q[j];

    unsigned mask_j = 0u;
#pragma unroll
    for (int s = 0; s < NSD; s++) mask_j |= g_pmask[s * NB + j];

    dred[j] = T_j;
    mred[j] = mask_j;
    __syncthreads();
    for (int o = 128; o > 0; o >>= 1) {
        if (j < o) { dred[j] += dred[j + o]; mred[j] |= mred[j + o]; }
        __syncthreads();
    }
    const double Gtot = dred[0];
    const int    utot = __popc(mred[0]);
    const int    u_j  = __popc(mask_j);
    __syncthreads();

    /* row_mse_j = (Sq_j - 2*T_j/B + Gtot/B^2) / D */
    double mse_j = ((double)qrow - 2.0 * T_j / (double)NB
                    + Gtot / (double)(NB * NB)) / (double)ND;
    dred[j] = mse_j;
    __syncthreads();
    for (int o = 128; o > 0; o >>= 1) {
        if (j < o) dred[j] += dred[j + o];
        __syncthreads();
    }
    const double total_mse = dred[0];
    __syncthreads();

    double cand = (1.0 - (double)f1) * (mse_j / total_mse)
                * ((double)u_j / (double)utot);
    dred[j] = cand;
    __syncthreads();
    for (int o = 128; o > 0; o >>= 1) {
        if (j < o) dred[j] = dred[j] > dred[j + o] ? dred[j] : dred[j + o];
        __syncthreads();
    }
    if (j == 0) {
        double p = dred[0] > 0.0 ? dred[0] : 0.0;
        g_p = (float)p;
        g_scale = (float)(1.0 / (1.0 - p));
        g_done = 0;                 /* reset for next graph replay */
    }
}

/* ------------------------- kernel 3: dropout ------------------------------ */
__global__ void k_dropout(const float4* __restrict__ X,
                          const float4* __restrict__ NZ,
                          float4* __restrict__ O, int n4) {
    const float p  = g_p;
    const float sc = g_scale;
    for (int i = blockIdx.x * blockDim.x + threadIdx.x; i < n4;
         i += gridDim.x * blockDim.x) {
        float4 x = X[i];
        float4 z = NZ[i];
        float4 o;
        o.x = (z.x >= p) ? x.x * sc : 0.0f;
        o.y = (z.y >= p) ? x.y * sc : 0.0f;
        o.z = (z.z >= p) ? x.z * sc : 0.0f;
        o.w = (z.w >= p) ? x.w * sc : 0.0f;
        O[i] = o;
    }
}

/* ------------------------- launch ---------------------------------------- */
extern "C" void kernel_launch(void* const* d_in, const int* in_sizes, int n_in,
                              void* d_out, int out_size) {
    const float* x  = (const float*)d_in[0];
    const float* nz = (const float*)d_in[1];
    float* out = (float*)d_out;
    const int n4 = (NB * ND) / 4;   /* 8388608 */

    cudaFuncSetAttribute(k_gram, cudaFuncAttributeMaxDynamicSharedMemorySize,
                         65536);

    k_gram<<<GRID_GRAM, 1024, 65536>>>(x);
    k_epilogue<<<NB, 256>>>();
    k_dropout<<<4736, 256>>>((const float4*)x, (const float4*)nz,
                             (float4*)out, n4);
}

// round 17
// speedup vs baseline: 1.0517x; 1.0517x over previous
#include <cuda_runtime.h>
#include <cuda_bf16.h>
#include <stdint.h>

#define NB 256
#define ND 131072
#define KC2 128                     /* fp32 cols per outer chunk (2 sub-tiles) */
#define TOTCH2 (ND / KC2)           /* 1024 */
#define NSD 42                      /* diag splits per diag quadrant */
#define NSO 63                      /* off-diag splits */
#define GRID_GRAM (2 * NSD + NSO)   /* 147 CTAs = 1 full wave */
#define NBNB (NB * NB)
#define SMEM_BYTES 131072           /* 2 buffers x (A 2x16KB + B 2x16KB) */

/* ------------------------- device scratch (static, no allocs) ------------ */
__device__ float    g_partials[(size_t)NSO * NBNB];     /* 16.1 MB */
__device__ float    g_psum[NSD * NB];
__device__ float    g_psumsq[NSD * NB];
__device__ unsigned g_pmask[NSD * NB];
__device__ double   g_T[NB];
__device__ float    g_acc1[NB];
__device__ unsigned g_done;          /* zero-init; reset by last CTA */
__device__ float    g_p;
__device__ float    g_scale;

/* ------------------------- helpers --------------------------------------- */
__device__ __forceinline__ uint32_t smem_u32(const void* p) {
    uint32_t a;
    asm("{ .reg .u64 t; cvta.to.shared.u64 t, %1; cvt.u32.u64 %0, t; }"
        : "=r"(a) : "l"(p));
    return a;
}
__device__ __forceinline__ uint32_t swz(uint32_t off) {
    return off ^ ((off >> 3) & 0x70);   /* SW128: bits[6:4] ^= bits[9:7] */
}
__device__ __forceinline__ uint32_t pack_bf16x2(float lo, float hi) {
    uint32_t r;
    asm("cvt.rn.bf16x2.f32 %0, %1, %2;" : "=r"(r) : "f"(hi), "f"(lo));
    return r;
}
__device__ __forceinline__ uint32_t round_bit(float v) {
    int iv = __float2int_rn(v);            /* ties-to-even == jnp.round */
    unsigned b = (unsigned)(iv + 16);      /* N(0,1): |round(x)| <= ~6  */
    return (b < 32u) ? (1u << b) : 0u;
}

#define LDSM4(r0_, r1_, r2_, r3_, addr)                                        \
    asm volatile("ldmatrix.sync.aligned.m8n8.x4.shared.b16 {%0,%1,%2,%3}, [%4];"\
                 : "=r"(r0_), "=r"(r1_), "=r"(r2_), "=r"(r3_) : "r"(addr))

#define MMA16816(d, a, b)                                                      \
    asm volatile("mma.sync.aligned.m16n8k16.row.col.f32.bf16.bf16.f32 "        \
                 "{%0,%1,%2,%3},{%4,%5,%6,%7},{%8,%9},{%0,%1,%2,%3};"          \
                 : "+f"((d)[0]), "+f"((d)[1]), "+f"((d)[2]), "+f"((d)[3])      \
                 : "r"((a)[0]), "r"((a)[1]), "r"((a)[2]), "r"((a)[3]),         \
                   "r"((b)[0]), "r"((b)[1]))

/* ------------------------- kernel 1: fused stats + bf16 Gram -------------- */
/* grid = 147 CTAs = single wave; 512 threads (16 warps) per CTA (R15 optimum:
   8w=104us, 16w=69.7us, 32w=80.5us -> RF-constrained sweet spot).
   This round: 128-col outer chunks (two 64-col sub-tiles), one barrier per
   outer chunk, LDG/MMA/STS staggered at sub-tile granularity.
     b in [0,42):   t=0 diag C[0:128,0:128]
     b in [42,84):  t=1 diag C[128:256,128:256]
     b in [84,147): t=2 offd C[0:128,128:256] (+ transpose quadrant)
   smem layout per buffer q (64KB): A(q,0),A(q,1),B(q,0),B(q,1) x 16KB. */
__global__ __launch_bounds__(512, 1) void k_gram(const float* __restrict__ X) {
    extern __shared__ unsigned char smem[];

    const int tid = threadIdx.x;
    const int wid = tid >> 5;
    const int L   = tid & 31;

    const int b = blockIdx.x;
    int t, s;
    if (b < NSD)            { t = 0; s = b; }
    else if (b < 2 * NSD)   { t = 1; s = b - NSD; }
    else                    { t = 2; s = b - 2 * NSD; }
    const int m0 = (t == 1) ? 128 : 0;
    const int n0 = (t == 0) ? 0 : 128;
    const bool offd = (t == 2);
    const int NSPL = offd ? NSO : NSD;

    const int kc0 = (s * TOTCH2) / NSPL;
    const int kc1 = ((s + 1) * TOTCH2) / NSPL;
    const int noch = kc1 - kc0;             /* outer 128-col chunks */
    const size_t kbase = (size_t)kc0 * KC2;

    /* loader mapping: 16 float4-columns x 32 row-groups, 4 rows/thread/subtile */
    const int c4 = tid & 15;
    const int rr = tid >> 4;                /* 0..31; rows rr + 32*i */
    const float* Ap = X + (size_t)(m0 + rr) * ND + kbase + c4 * 4;
    const float* Bp = X + (size_t)(n0 + rr) * ND + kbase + c4 * 4;
    const size_t rstride = (size_t)32 * ND;

    const uint32_t smem_base = smem_u32(smem);

    float    sacc[4], qacc[4];
    uint32_t macc[4];
#pragma unroll
    for (int i = 0; i < 4; i++) { sacc[i] = 0.f; qacc[i] = 0.f; macc[i] = 0u; }

    float4 va[4], vb[4];

    /* ---- store one sub-tile (with stats for diag CTAs) ---- */
#define STORE_SUB(qbuf, usub)                                                  \
    do {                                                                       \
        unsigned char* a_t = smem + (qbuf) * 65536 + (usub) * 16384;           \
        unsigned char* b_t = a_t + 32768;                                      \
        _Pragma("unroll")                                                      \
        for (int i = 0; i < 4; i++) {                                          \
            if (!offd) {                                                       \
                float4 w = va[i];                                              \
                sacc[i] += (w.x + w.y) + (w.z + w.w);                          \
                qacc[i] += w.x * w.x + w.y * w.y + w.z * w.z + w.w * w.w;      \
                macc[i] |= round_bit(w.x) | round_bit(w.y) |                   \
                           round_bit(w.z) | round_bit(w.w);                    \
            }                                                                  \
            uint32_t off = swz((uint32_t)((rr + 32 * i) * 128 + c4 * 8));      \
            uint2 w2;                                                          \
            w2.x = pack_bf16x2(va[i].x, va[i].y);                              \
            w2.y = pack_bf16x2(va[i].z, va[i].w);                              \
            *(uint2*)(a_t + off) = w2;                                         \
            if (offd) {                                                        \
                uint2 u2;                                                      \
                u2.x = pack_bf16x2(vb[i].x, vb[i].y);                          \
                u2.y = pack_bf16x2(vb[i].z, vb[i].w);                          \
                *(uint2*)(b_t + off) = u2;                                     \
            }                                                                  \
        }                                                                      \
    } while (0)

#define LOAD_SUB(hh, usub)                                                     \
    do {                                                                       \
        const float* pa = Ap + (size_t)(hh) * KC2 + (usub) * 64;               \
        _Pragma("unroll")                                                      \
        for (int i = 0; i < 4; i++) va[i] = *(const float4*)(pa + i * rstride);\
        if (offd) {                                                            \
            const float* pb = Bp + (size_t)(hh) * KC2 + (usub) * 64;           \
            _Pragma("unroll")                                                  \
            for (int i = 0; i < 4; i++) vb[i] = *(const float4*)(pb + i * rstride);\
        }                                                                      \
    } while (0)

    /* ---- prologue: outer chunk 0 -> buffer 0 ---- */
    LOAD_SUB(0, 0);
    STORE_SUB(0, 0);
    LOAD_SUB(0, 1);
    STORE_SUB(0, 1);
    __syncthreads();

    /* ---- mainloop ---- */
    const int wm = wid & 3;          /* 4 m-blocks of 32 rows */
    const int wn = wid >> 2;         /* 4 n-blocks of 32 cols */
    float c[2][4][4];
#pragma unroll
    for (int mf = 0; mf < 2; mf++)
#pragma unroll
        for (int nf = 0; nf < 4; nf++)
#pragma unroll
            for (int r = 0; r < 4; r++) c[mf][nf][r] = 0.f;

    const uint32_t arow_l = (uint32_t)(wm * 32 + (L & 15));
    const uint32_t ak_l   = (uint32_t)(((L >> 4) & 1) * 16);
    const uint32_t bn_l   = (uint32_t)(wn * 32 + (L & 7) + ((L >> 4) & 1) * 8);
    const uint32_t bk_l   = (uint32_t)(((L >> 3) & 1) * 16);

#define MMA_SUB(qbuf, usub)                                                    \
    do {                                                                       \
        const uint32_t abase = smem_base + (qbuf) * 65536u + (usub) * 16384u;  \
        const uint32_t bbase = offd ? (abase + 32768u) : abase;                \
        _Pragma("unroll")                                                      \
        for (int ks = 0; ks < 4; ks++) {                                       \
            uint32_t a[2][4], bb[4][2];                                        \
            _Pragma("unroll")                                                  \
            for (int mf = 0; mf < 2; mf++) {                                   \
                uint32_t addr = abase +                                        \
                    swz((arow_l + mf * 16) * 128 + (uint32_t)ks * 32 + ak_l);  \
                LDSM4(a[mf][0], a[mf][1], a[mf][2], a[mf][3], addr);           \
            }                                                                  \
            _Pragma("unroll")                                                  \
            for (int ng = 0; ng < 2; ng++) {                                   \
                uint32_t addr = bbase +                                        \
                    swz((bn_l + ng * 16) * 128 + (uint32_t)ks * 32 + bk_l);    \
                LDSM4(bb[2 * ng][0], bb[2 * ng][1], bb[2 * ng + 1][0],         \
                      bb[2 * ng + 1][1], addr);                                \
            }                                                                  \
            _Pragma("unroll")                                                  \
            for (int mf = 0; mf < 2; mf++)                                     \
                _Pragma("unroll")                                              \
                for (int nf = 0; nf < 4; nf++)                                 \
                    MMA16816(c[mf][nf], a[mf], bb[nf]);                        \
        }                                                                      \
    } while (0)

    for (int h = 0; h < noch; ++h) {
        const int cur = h & 1, nxt = cur ^ 1;
        const bool more = (h + 1 < noch);

        if (more) LOAD_SUB(h + 1, 0);
        MMA_SUB(cur, 0);
        if (more) {
            STORE_SUB(nxt, 0);
            LOAD_SUB(h + 1, 1);
        }
        MMA_SUB(cur, 1);
        if (more) STORE_SUB(nxt, 1);
        __syncthreads();
    }

    /* ---- per-split row stats (deterministic: no fp32 atomics) ----
       the 16 threads sharing row-group rr are consecutive tids -> shfl w16 */
    if (!offd) {
#pragma unroll
        for (int i = 0; i < 4; i++) {
            float ss = sacc[i], qq = qacc[i];
            uint32_t mm = macc[i];
#pragma unroll
            for (int o = 8; o > 0; o >>= 1) {
                ss += __shfl_down_sync(0xffffffffu, ss, o, 16);
                qq += __shfl_down_sync(0xffffffffu, qq, o, 16);
                mm |= __shfl_down_sync(0xffffffffu, mm, o, 16);
            }
            if (c4 == 0) {
                int row = m0 + rr + 32 * i;
                g_psum[s * NB + row]   = ss;
                g_psumsq[s * NB + row] = qq;
                g_pmask[s * NB + row]  = mm;
            }
        }
    }

    /* ---- epilogue: accumulators -> per-split partial Gram ---- */
    {
        const int gid = L >> 2, tig = L & 3;
        float* P = g_partials + (size_t)s * NBNB;
#pragma unroll
        for (int mf = 0; mf < 2; mf++) {
#pragma unroll
            for (int nf = 0; nf < 4; nf++) {
                int row = m0 + wm * 32 + mf * 16 + gid;
                int col = n0 + wn * 32 + nf * 8 + tig * 2;
                float2 lo = make_float2(c[mf][nf][0], c[mf][nf][1]);
                float2 hi = make_float2(c[mf][nf][2], c[mf][nf][3]);
                *(float2*)(P + (size_t)row * NB + col)       = lo;
                *(float2*)(P + (size_t)(row + 8) * NB + col) = hi;
                if (offd) {   /* transpose quadrant */
                    P[(size_t)col * NB + row]           = c[mf][nf][0];
                    P[(size_t)(col + 1) * NB + row]     = c[mf][nf][1];
                    P[(size_t)col * NB + row + 8]       = c[mf][nf][2];
                    P[(size_t)(col + 1) * NB + row + 8] = c[mf][nf][3];
                }
            }
        }
    }
#undef STORE_SUB
#undef LOAD_SUB
#undef MMA_SUB
}

/* ------------------------- kernel 2: fused epilogue ----------------------- */
/* 256 CTAs, one per Gram row i:
     - reduce partial slabs directly (diag quadrant sums NSD slabs, off-diag
       NSO slabs; coalesced, L2-resident)
     - per-row |corr| sum and row total T_i
     - the LAST CTA to finish (atomic counter) computes p; counter reset so
       every graph replay behaves identically. */
__global__ __launch_bounds__(256) void k_epilogue() {
    __shared__ float    sh_s[NB], sh_inv[NB], sh_q[NB];
    __shared__ double   dred[NB];
    __shared__ float    fred[NB];
    __shared__ unsigned mred[NB];
    __shared__ bool     is_last;

    const int j = threadIdx.x;
    const int i = blockIdx.x;

    /* per-column stats (recomputed per CTA; L2-hot) */
    float s_j = 0.f, q_j = 0.f;
#pragma unroll
    for (int s = 0; s < NSD; s++) {
        s_j += g_psum[s * NB + j];
        q_j += g_psumsq[s * NB + j];
    }
    const float invD  = 1.0f / (float)ND;
    const float invD1 = 1.0f / (float)(ND - 1);
    sh_s[j]   = s_j;
    sh_q[j]   = q_j;
    sh_inv[j] = rsqrtf((q_j - s_j * s_j * invD) * invD1);
    __syncthreads();

    /* G_ij = sum over slabs of partials (quadrant-dependent count) */
    const int cnt = ((i < 128) == (j < 128)) ? NSD : NSO;
    const float* P = g_partials + (size_t)i * NB + j;
    float g = 0.f;
#pragma unroll 4
    for (int s = 0; s < cnt; s++) g += P[(size_t)s * NBNB];
    if (j == i) g = sh_q[i];                   /* exact diagonal */

    const float s_i = sh_s[i], inv_i = sh_inv[i];
    float cov  = (g - s_i * sh_s[j] * invD) * invD1;
    float corr = cov * inv_i * sh_inv[j];
    corr = fminf(1.0f, fmaxf(-1.0f, corr));

    dred[j] = (double)g;
    fred[j] = fabsf(corr);
    __syncthreads();
    for (int o = 128; o > 0; o >>= 1) {
        if (j < o) { dred[j] += dred[j + o]; fred[j] += fred[j + o]; }
        __syncthreads();
    }
    if (j == 0) {
        g_T[i]    = dred[0];
        g_acc1[i] = fred[0];
        __threadfence();
        unsigned v = atomicAdd(&g_done, 1u);
        is_last = (v == NB - 1);
    }
    __syncthreads();
    if (!is_last) return;
    __threadfence();

    /* ---- final scalar phase (one CTA); thread j plays role of row j ---- */
    const double T_j   = g_T[j];
    const float  f1    = g_acc1[j] * (1.0f / (float)NB);
    const float  qrow  = sh_q[j];

    unsigned mask_j = 0u;
#pragma unroll
    for (int s = 0; s < NSD; s++) mask_j |= g_pmask[s * NB + j];

    dred[j] = T_j;
    mred[j] = mask_j;
    __syncthreads();
    for (int o = 128; o > 0; o >>= 1) {
        if (j < o) { dred[j] += dred[j + o]; mred[j] |= mred[j + o]; }
        __syncthreads();
    }
    const double Gtot = dred[0];
    const int    utot = __popc(mred[0]);
    const int    u_j  = __popc(mask_j);
    __syncthreads();

    /* row_mse_j = (Sq_j - 2*T_j/B + Gtot/B^2) / D */
    double mse_j = ((double)qrow - 2.0 * T_j / (double)NB
                    + Gtot / (double)(NB * NB)) / (double)ND;
    dred[j] = mse_j;
    __syncthreads();
    for (int o = 128; o > 0; o >>= 1) {
        if (j < o) dred[j] += dred[j + o];
        __syncthreads();
    }
    const double total_mse = dred[0];
    __syncthreads();

    double cand = (1.0 - (double)f1) * (mse_j / total_mse)
                * ((double)u_j / (double)utot);
    dred[j] = cand;
    __syncthreads();
    for (int o = 128; o > 0; o >>= 1) {
        if (j < o) dred[j] = dred[j] > dred[j + o] ? dred[j] : dred[j + o];
        __syncthreads();
    }
    if (j == 0) {
        double p = dred[0] > 0.0 ? dred[0] : 0.0;
        g_p = (float)p;
        g_scale = (float)(1.0 / (1.0 - p));
        g_done = 0;                 /* reset for next graph replay */
    }
}

/* ------------------------- kernel 3: dropout ------------------------------ */
__global__ void k_dropout(const float4* __restrict__ X,
                          const float4* __restrict__ NZ,
                          float4* __restrict__ O, int n4) {
    const float p  = g_p;
    const float sc = g_scale;
    for (int i = blockIdx.x * blockDim.x + threadIdx.x; i < n4;
         i += gridDim.x * blockDim.x) {
        float4 x = X[i];
        float4 z = NZ[i];
        float4 o;
        o.x = (z.x >= p) ? x.x * sc : 0.0f;
        o.y = (z.y >= p) ? x.y * sc : 0.0f;
        o.z = (z.z >= p) ? x.z * sc : 0.0f;
        o.w = (z.w >= p) ? x.w * sc : 0.0f;
        O[i] = o;
    }
}

/* ------------------------- launch ---------------------------------------- */
extern "C" void kernel_launch(void* const* d_in, const int* in_sizes, int n_in,
                              void* d_out, int out_size) {
    const float* x  = (const float*)d_in[0];
    const float* nz = (const float*)d_in[1];
    float* out = (float*)d_out;
    const int n4 = (NB * ND) / 4;   /* 8388608 */

    cudaFuncSetAttribute(k_gram, cudaFuncAttributeMaxDynamicSharedMemorySize,
                         SMEM_BYTES);

    k_gram<<<GRID_GRAM, 512, SMEM_BYTES>>>(x);
    k_epilogue<<<NB, 256>>>();
    k_dropout<<<4736, 256>>>((const float4*)x, (const float4*)nz,
                             (float4*)out, n4);
}